// round 14
// baseline (speedup 1.0000x reference)
#include <cuda_runtime.h>
#include <cuda_bf16.h>
#include <stdint.h>
#include <math.h>

// Problem constants (MetaS4: B=1024, H=1024, N=32)
#define BSZ 1024
#define HD  1024
#define NS  32

// ---------------------------------------------------------------------------
// Device scratch (allocation-free rule)
// g_Bhi/g_Blo hold W in GLU-PERMUTED row order: row 2j = W[j], row 2j+1 = W[H+j]
// ---------------------------------------------------------------------------
__device__ __align__(256) __nv_bfloat16 g_Ahi[BSZ * HD];       // y hi  [M,K]
__device__ __align__(256) __nv_bfloat16 g_Alo[BSZ * HD];       // y lo
__device__ __align__(256) __nv_bfloat16 g_Bhi[2 * HD * HD];    // Wperm hi [2H,K]
__device__ __align__(256) __nv_bfloat16 g_Blo[2 * HD * HD];    // Wperm lo

// ---------------------------------------------------------------------------
// PTX helpers (baseline ISA only — no tcgen05 on this build's ptx target)
// ---------------------------------------------------------------------------
__device__ __forceinline__ uint32_t smem_to_u32(const void* p) {
    uint32_t a;
    asm("{ .reg .u64 t; cvta.to.shared.u64 t, %1; cvt.u32.u64 %0, t; }"
        : "=r"(a) : "l"(p));
    return a;
}
__device__ __forceinline__ void cp_async16(uint32_t smem_addr, const void* gptr) {
    asm volatile("cp.async.cg.shared.global [%0], [%1], 16;\n"
                 :: "r"(smem_addr), "l"(gptr) : "memory");
}
__device__ __forceinline__ void cp_async_commit() {
    asm volatile("cp.async.commit_group;\n" ::: "memory");
}
__device__ __forceinline__ void cp_async_wait1() {
    asm volatile("cp.async.wait_group 1;\n" ::: "memory");
}
__device__ __forceinline__ void cp_async_wait0() {
    asm volatile("cp.async.wait_group 0;\n" ::: "memory");
}

#define LDMATRIX_X4(r0, r1, r2, r3, addr) \
    asm volatile("ldmatrix.sync.aligned.m8n8.x4.shared.b16 {%0,%1,%2,%3}, [%4];" \
        : "=r"(r0), "=r"(r1), "=r"(r2), "=r"(r3) : "r"(addr))

#define MMA_16816(acc, a, b0, b1) \
    asm volatile("mma.sync.aligned.m16n8k16.row.col.f32.bf16.bf16.f32 " \
        "{%0,%1,%2,%3}, {%4,%5,%6,%7}, {%8,%9}, {%0,%1,%2,%3};" \
        : "+f"((acc)[0]), "+f"((acc)[1]), "+f"((acc)[2]), "+f"((acc)[3]) \
        : "r"((a)[0]), "r"((a)[1]), "r"((a)[2]), "r"((a)[3]), \
          "r"(b0), "r"(b1))

// Swizzled smem address for a [rows][32 bf16] tile (64 B rows, 4x16B slots).
__device__ __forceinline__ uint32_t swz_addr(uint32_t tile_base, int row, int slot) {
    int s = (slot + ((row >> 1) & 3)) & 3;
    return tile_base + row * 64 + s * 16;
}

// ---------------------------------------------------------------------------
// Kernel 1 (FUSED): blocks [0, 2048)   -> convert W -> bf16 hi/lo (permuted)
//                   blocks [2048, ...) -> s4 state update (R6 mapping)
// ---------------------------------------------------------------------------
#define CONVW_BLOCKS 2048
#define S4_BLOCKS    (BSZ * HD * 8 / 256)    // 32768

__global__ __launch_bounds__(256) void fused_update_kernel(
    const float* __restrict__ u,
    const float* __restrict__ st_re, const float* __restrict__ st_im,
    const float* __restrict__ dA_re, const float* __restrict__ dA_im,
    const float* __restrict__ dB_re, const float* __restrict__ dB_im,
    const float* __restrict__ C_re,  const float* __restrict__ C_im,
    const float* __restrict__ D,     const float* __restrict__ W,
    float* __restrict__ ns_re, float* __restrict__ ns_im)
{
    if (blockIdx.x < CONVW_BLOCKS) {
        // ---- convertW path ----
        int i  = blockIdx.x * 256 + threadIdx.x;
        int i4 = i * 4;
        int row = i4 >> 10;          // / HD
        int col = i4 & (HD - 1);
        int drow = (row < HD) ? (2 * row) : (2 * (row - HD) + 1);
        size_t dst = (size_t)drow * HD + col;

        float4 w = *(const float4*)(W + i4);

        __nv_bfloat16 h0 = __float2bfloat16(w.x);
        __nv_bfloat16 h1 = __float2bfloat16(w.y);
        __nv_bfloat16 h2 = __float2bfloat16(w.z);
        __nv_bfloat16 h3 = __float2bfloat16(w.w);
        __nv_bfloat16 l0 = __float2bfloat16(w.x - __bfloat162float(h0));
        __nv_bfloat16 l1 = __float2bfloat16(w.y - __bfloat162float(h1));
        __nv_bfloat16 l2 = __float2bfloat16(w.z - __bfloat162float(h2));
        __nv_bfloat16 l3 = __float2bfloat16(w.w - __bfloat162float(h3));

        uint32_t hp0 = ((uint32_t)__bfloat16_as_ushort(h1) << 16) | __bfloat16_as_ushort(h0);
        uint32_t hp1 = ((uint32_t)__bfloat16_as_ushort(h3) << 16) | __bfloat16_as_ushort(h2);
        uint32_t lp0 = ((uint32_t)__bfloat16_as_ushort(l1) << 16) | __bfloat16_as_ushort(l0);
        uint32_t lp1 = ((uint32_t)__bfloat16_as_ushort(l3) << 16) | __bfloat16_as_ushort(l2);
        *(uint2*)(g_Bhi + dst) = make_uint2(hp0, hp1);
        *(uint2*)(g_Blo + dst) = make_uint2(lp0, lp1);
        return;
    }

    // ---- s4 path ----
    int t = (blockIdx.x - CONVW_BLOCKS) * 256 + threadIdx.x;
    int g = t >> 3;            // (b,h) flat id
    int q = t & 7;             // 4-n group index
    int h = g & (HD - 1);

    long base = (long)g * NS + q * 4;
    int  ph   = h * NS + q * 4;

    float4 sre = __ldcs((const float4*)(st_re + base));
    float4 sim = __ldcs((const float4*)(st_im + base));
    float4 are = *(const float4*)(dA_re + ph);
    float4 aim = *(const float4*)(dA_im + ph);
    float4 bre = *(const float4*)(dB_re + ph);
    float4 bim = *(const float4*)(dB_im + ph);
    float4 cre = *(const float4*)(C_re  + ph);
    float4 cim = *(const float4*)(C_im  + ph);
    float  uu  = u[g];

    float4 nre, nim;
    nre.x = fmaf(are.x, sre.x, fmaf(-aim.x, sim.x, bre.x * uu));
    nre.y = fmaf(are.y, sre.y, fmaf(-aim.y, sim.y, bre.y * uu));
    nre.z = fmaf(are.z, sre.z, fmaf(-aim.z, sim.z, bre.z * uu));
    nre.w = fmaf(are.w, sre.w, fmaf(-aim.w, sim.w, bre.w * uu));
    nim.x = fmaf(are.x, sim.x, fmaf( aim.x, sre.x, bim.x * uu));
    nim.y = fmaf(are.y, sim.y, fmaf( aim.y, sre.y, bim.y * uu));
    nim.z = fmaf(are.z, sim.z, fmaf( aim.z, sre.z, bim.z * uu));
    nim.w = fmaf(are.w, sim.w, fmaf( aim.w, sre.w, bim.w * uu));

    __stcs((float4*)(ns_re + base), nre);
    __stcs((float4*)(ns_im + base), nim);

    float p = fmaf(cre.x, nre.x, -cim.x * nim.x)
            + fmaf(cre.y, nre.y, -cim.y * nim.y)
            + fmaf(cre.z, nre.z, -cim.z * nim.z)
            + fmaf(cre.w, nre.w, -cim.w * nim.w);
    p += __shfl_xor_sync(0xFFFFFFFFu, p, 4);
    p += __shfl_xor_sync(0xFFFFFFFFu, p, 2);
    p += __shfl_xor_sync(0xFFFFFFFFu, p, 1);

    if (q == 0) {
        float y = 2.0f * p + uu * D[h];
        float gel = 0.5f * y * (1.0f + erff(y * 0.7071067811865476f));
        __nv_bfloat16 hi = __float2bfloat16(gel);
        __nv_bfloat16 lo = __float2bfloat16(gel - __bfloat162float(hi));
        g_Ahi[g] = hi;
        g_Alo[g] = lo;
    }
}

// ---------------------------------------------------------------------------
// Kernel 2: bf16-split GEMM via mma.sync.m16n8k16 + fused GLU epilogue.
// CTA tile 128(M) x 64(N-perm), 8 warps (2M x 4N), warp tile 64x16.
// Grid (32, 8) = 256 CTAs, 2 CTAs/SM resident -> occupancy 25%,
// cross-CTA latency hiding for syncs and ldmatrix->MMA chains.
// ---------------------------------------------------------------------------
#define GT       256
#define TILE_M   128
#define TILE_N   64
#define KC       32
#define NKC      (HD / KC)            // 32
#define TILE_AB  (128 * KC * 2)       // 8192 bytes (A tiles, 128 rows)
#define TILE_BB  (64 * KC * 2)        // 4096 bytes (B tiles, 64 rows)
#define STAGE_B  (2 * TILE_AB + 2 * TILE_BB)  // 24576
#define GEMM_SMEM (2 * STAGE_B)       // 49152
#define OFF_AHI  0
#define OFF_ALO  TILE_AB
#define OFF_BHI  (2 * TILE_AB)
#define OFF_BLO  (2 * TILE_AB + TILE_BB)

__device__ __forceinline__ void load_stage(
    uint32_t st, int m0, int n0, int kc, int t)
{
    // A tiles: 512 segs each; B tiles: 256 segs each; total 1536; 256 thr -> 6
    #pragma unroll
    for (int i = 0; i < 6; i++) {
        int idx = i * GT + t;
        const __nv_bfloat16* gb;
        int row0, seg;
        uint32_t toff;
        if (idx < 512)        { gb = g_Ahi; row0 = m0; seg = idx;        toff = OFF_AHI; }
        else if (idx < 1024)  { gb = g_Alo; row0 = m0; seg = idx - 512;  toff = OFF_ALO; }
        else if (idx < 1280)  { gb = g_Bhi; row0 = n0; seg = idx - 1024; toff = OFF_BHI; }
        else                  { gb = g_Blo; row0 = n0; seg = idx - 1280; toff = OFF_BLO; }
        int row  = seg >> 2;
        int slot = seg & 3;
        const char* g = (const char*)(gb + (size_t)(row0 + row) * HD + kc * KC)
                        + slot * 16;
        cp_async16(swz_addr(st + toff, row, slot), g);
    }
}

__global__ __launch_bounds__(GT, 2) void gemm_tc_kernel(
    const float* __restrict__ bias, float* __restrict__ out)
{
    extern __shared__ char smem[];
    uint32_t sb = smem_to_u32(smem);
    int t    = threadIdx.x;
    int wid  = t >> 5;
    int lane = t & 31;
    int wm   = wid & 1;              // M half (0/1)
    int wn   = wid >> 1;             // N quarter (0..3), 16 perm-cols each

    int n0 = blockIdx.x * TILE_N;    // permuted-W row range
    int m0 = blockIdx.y * TILE_M;

    float acc[4][2][4];
    #pragma unroll
    for (int mi = 0; mi < 4; mi++)
        #pragma unroll
        for (int ni = 0; ni < 2; ni++)
            #pragma unroll
            for (int r = 0; r < 4; r++)
                acc[mi][ni][r] = 0.0f;

    // Prologue
    load_stage(sb, m0, n0, 0, t);
    cp_async_commit();

    int lrow  = lane & 15;
    int lslot = lane >> 4;

    for (int kc = 0; kc < NKC; kc++) {
        uint32_t stage = sb + (kc & 1) * STAGE_B;

        if (kc + 1 < NKC) {
            load_stage(sb + ((kc + 1) & 1) * STAGE_B, m0, n0, kc + 1, t);
            cp_async_commit();
            cp_async_wait1();
        } else {
            cp_async_wait0();
        }
        __syncthreads();

        uint32_t stAhi = stage + OFF_AHI;
        uint32_t stAlo = stage + OFF_ALO;
        uint32_t stBhi = stage + OFF_BHI;
        uint32_t stBlo = stage + OFF_BLO;

        #pragma unroll
        for (int kk = 0; kk < 2; kk++) {
            uint32_t a_hi[4][4], a_lo[4][4], b_hi[2][2], b_lo[2][2];

            #pragma unroll
            for (int mi = 0; mi < 4; mi++) {
                int row = wm * 64 + mi * 16 + lrow;
                int slt = 2 * kk + lslot;
                LDMATRIX_X4(a_hi[mi][0], a_hi[mi][1], a_hi[mi][2], a_hi[mi][3],
                            swz_addr(stAhi, row, slt));
                LDMATRIX_X4(a_lo[mi][0], a_lo[mi][1], a_lo[mi][2], a_lo[mi][3],
                            swz_addr(stAlo, row, slt));
            }
            {
                int row = wn * 16 + lrow;
                int slt = 2 * kk + lslot;
                uint32_t q0, q1, q2, q3;
                LDMATRIX_X4(q0, q1, q2, q3, swz_addr(stBhi, row, slt));
                b_hi[0][0] = q0; b_hi[0][1] = q2;
                b_hi[1][0] = q1; b_hi[1][1] = q3;
                LDMATRIX_X4(q0, q1, q2, q3, swz_addr(stBlo, row, slt));
                b_lo[0][0] = q0; b_lo[0][1] = q2;
                b_lo[1][0] = q1; b_lo[1][1] = q3;
            }

            // Term 1: hi * hi
            #pragma unroll
            for (int mi = 0; mi < 4; mi++)
                #pragma unroll
                for (int ni = 0; ni < 2; ni++)
                    MMA_16816(acc[mi][ni], a_hi[mi], b_hi[ni][0], b_hi[ni][1]);
            // Term 2: hi * lo
            #pragma unroll
            for (int mi = 0; mi < 4; mi++)
                #pragma unroll
                for (int ni = 0; ni < 2; ni++)
                    MMA_16816(acc[mi][ni], a_hi[mi], b_lo[ni][0], b_lo[ni][1]);
            // Term 3: lo * hi
            #pragma unroll
            for (int mi = 0; mi < 4; mi++)
                #pragma unroll
                for (int ni = 0; ni < 2; ni++)
                    MMA_16816(acc[mi][ni], a_lo[mi], b_hi[ni][0], b_hi[ni][1]);
        }
        __syncthreads();
    }

    // Fused GLU epilogue.
    int tr = lane >> 2;               // 0..7
    int tc = (lane & 3) * 2;
    int r_base = m0 + wm * 64;
    int c_base = n0 + wn * 16;
    #pragma unroll
    for (int mi = 0; mi < 4; mi++) {
        #pragma unroll
        for (int ni = 0; ni < 2; ni++) {
            int r = r_base + mi * 16 + tr;
            int j = (c_base + ni * 8 + tc) >> 1;
            float b0 = bias[j], b1 = bias[HD + j];
            float z1a = acc[mi][ni][0] + b0;
            float z2a = acc[mi][ni][1] + b1;
            float z1b = acc[mi][ni][2] + b0;
            float z2b = acc[mi][ni][3] + b1;
            out[(size_t)r * HD + j]       = z1a * (1.0f / (1.0f + __expf(-z2a)));
            out[(size_t)(r + 8) * HD + j] = z1b * (1.0f / (1.0f + __expf(-z2b)));
        }
    }
}

// ---------------------------------------------------------------------------
// launch
// ---------------------------------------------------------------------------
extern "C" void kernel_launch(void* const* d_in, const int* in_sizes, int n_in,
                              void* d_out, int out_size)
{
    const float* u     = (const float*)d_in[0];
    const float* st_re = (const float*)d_in[1];
    const float* st_im = (const float*)d_in[2];
    const float* dA_re = (const float*)d_in[3];
    const float* dA_im = (const float*)d_in[4];
    const float* dB_re = (const float*)d_in[5];
    const float* dB_im = (const float*)d_in[6];
    const float* C_re  = (const float*)d_in[7];
    const float* C_im  = (const float*)d_in[8];
    const float* D     = (const float*)d_in[9];
    const float* W     = (const float*)d_in[10];
    const float* bias  = (const float*)d_in[11];

    float* out   = (float*)d_out;
    float* y_out = out;                                    // [B, H]
    float* ns_re = out + (size_t)BSZ * HD;                 // [B, H, N]
    float* ns_im = out + (size_t)BSZ * HD + (size_t)BSZ * HD * NS;

    // 1) fused: convertW + s4 update
    fused_update_kernel<<<CONVW_BLOCKS + S4_BLOCKS, 256>>>(
        u, st_re, st_im, dA_re, dA_im, dB_re, dB_im, C_re, C_im, D, W,
        ns_re, ns_im);

    // 2) tensor-core (HMMA) GEMM + fused GLU -> y_out
    static bool attr_set = false;
    if (!attr_set) {
        cudaFuncSetAttribute(gemm_tc_kernel,
                             cudaFuncAttributeMaxDynamicSharedMemorySize,
                             GEMM_SMEM);
        attr_set = true;
    }
    {
        dim3 grid(2 * HD / TILE_N, BSZ / TILE_M);   // (32, 8)
        gemm_tc_kernel<<<grid, GT, GEMM_SMEM>>>(bias, y_out);
    }

    (void)in_sizes; (void)n_in; (void)out_size;
}

// round 15
// speedup vs baseline: 1.0911x; 1.0911x over previous
#include <cuda_runtime.h>
#include <cuda_fp16.h>
#include <stdint.h>
#include <math.h>

// Problem constants (MetaS4: B=1024, H=1024, N=32)
#define BSZ 1024
#define HD  1024
#define NS  32

// ---------------------------------------------------------------------------
// Device scratch (allocation-free rule)
// g_Bh holds W in GLU-PERMUTED row order: row 2j = W[j], row 2j+1 = W[H+j]
// A (y) is split hi+lo in fp16 (22-bit effective); W is single fp16.
// ---------------------------------------------------------------------------
__device__ __align__(256) __half g_Ahi[BSZ * HD];       // y hi  [M,K]
__device__ __align__(256) __half g_Alo[BSZ * HD];       // y lo
__device__ __align__(256) __half g_Bh [2 * HD * HD];    // Wperm [2H,K]

// ---------------------------------------------------------------------------
// PTX helpers (baseline ISA only — no tcgen05 on this build's ptx target)
// ---------------------------------------------------------------------------
__device__ __forceinline__ uint32_t smem_to_u32(const void* p) {
    uint32_t a;
    asm("{ .reg .u64 t; cvta.to.shared.u64 t, %1; cvt.u32.u64 %0, t; }"
        : "=r"(a) : "l"(p));
    return a;
}
__device__ __forceinline__ void cp_async16(uint32_t smem_addr, const void* gptr) {
    asm volatile("cp.async.cg.shared.global [%0], [%1], 16;\n"
                 :: "r"(smem_addr), "l"(gptr) : "memory");
}
__device__ __forceinline__ void cp_async_commit() {
    asm volatile("cp.async.commit_group;\n" ::: "memory");
}
__device__ __forceinline__ void cp_async_wait1() {
    asm volatile("cp.async.wait_group 1;\n" ::: "memory");
}
__device__ __forceinline__ void cp_async_wait0() {
    asm volatile("cp.async.wait_group 0;\n" ::: "memory");
}

#define LDMATRIX_X4(r0, r1, r2, r3, addr) \
    asm volatile("ldmatrix.sync.aligned.m8n8.x4.shared.b16 {%0,%1,%2,%3}, [%4];" \
        : "=r"(r0), "=r"(r1), "=r"(r2), "=r"(r3) : "r"(addr))

#define MMA_16816_F16(acc, a, b0, b1) \
    asm volatile("mma.sync.aligned.m16n8k16.row.col.f32.f16.f16.f32 " \
        "{%0,%1,%2,%3}, {%4,%5,%6,%7}, {%8,%9}, {%0,%1,%2,%3};" \
        : "+f"((acc)[0]), "+f"((acc)[1]), "+f"((acc)[2]), "+f"((acc)[3]) \
        : "r"((a)[0]), "r"((a)[1]), "r"((a)[2]), "r"((a)[3]), \
          "r"(b0), "r"(b1))

// Swizzled smem address for a [rows][32 fp16] tile (64 B rows, 4x16B slots).
__device__ __forceinline__ uint32_t swz_addr(uint32_t tile_base, int row, int slot) {
    int s = (slot + ((row >> 1) & 3)) & 3;
    return tile_base + row * 64 + s * 16;
}

// ---------------------------------------------------------------------------
// Kernel 1 (FUSED): blocks [0, 2048)   -> convert W -> fp16 (permuted)
//                   blocks [2048, ...) -> s4 state update (R6 mapping)
// ---------------------------------------------------------------------------
#define CONVW_BLOCKS 2048
#define S4_BLOCKS    (BSZ * HD * 8 / 256)    // 32768

__global__ __launch_bounds__(256) void fused_update_kernel(
    const float* __restrict__ u,
    const float* __restrict__ st_re, const float* __restrict__ st_im,
    const float* __restrict__ dA_re, const float* __restrict__ dA_im,
    const float* __restrict__ dB_re, const float* __restrict__ dB_im,
    const float* __restrict__ C_re,  const float* __restrict__ C_im,
    const float* __restrict__ D,     const float* __restrict__ W,
    float* __restrict__ ns_re, float* __restrict__ ns_im)
{
    if (blockIdx.x < CONVW_BLOCKS) {
        // ---- convertW path: fp16, GLU-permuted rows ----
        int i  = blockIdx.x * 256 + threadIdx.x;
        int i4 = i * 4;
        int row = i4 >> 10;          // / HD
        int col = i4 & (HD - 1);
        int drow = (row < HD) ? (2 * row) : (2 * (row - HD) + 1);
        size_t dst = (size_t)drow * HD + col;

        float4 w = *(const float4*)(W + i4);
        __half h0 = __float2half(w.x);
        __half h1 = __float2half(w.y);
        __half h2 = __float2half(w.z);
        __half h3 = __float2half(w.w);
        uint32_t p0 = ((uint32_t)__half_as_ushort(h1) << 16) | __half_as_ushort(h0);
        uint32_t p1 = ((uint32_t)__half_as_ushort(h3) << 16) | __half_as_ushort(h2);
        *(uint2*)(g_Bh + dst) = make_uint2(p0, p1);
        return;
    }

    // ---- s4 path ----
    int t = (blockIdx.x - CONVW_BLOCKS) * 256 + threadIdx.x;
    int g = t >> 3;            // (b,h) flat id
    int q = t & 7;             // 4-n group index
    int h = g & (HD - 1);

    long base = (long)g * NS + q * 4;
    int  ph   = h * NS + q * 4;

    float4 sre = __ldcs((const float4*)(st_re + base));
    float4 sim = __ldcs((const float4*)(st_im + base));
    float4 are = *(const float4*)(dA_re + ph);
    float4 aim = *(const float4*)(dA_im + ph);
    float4 bre = *(const float4*)(dB_re + ph);
    float4 bim = *(const float4*)(dB_im + ph);
    float4 cre = *(const float4*)(C_re  + ph);
    float4 cim = *(const float4*)(C_im  + ph);
    float  uu  = u[g];

    float4 nre, nim;
    nre.x = fmaf(are.x, sre.x, fmaf(-aim.x, sim.x, bre.x * uu));
    nre.y = fmaf(are.y, sre.y, fmaf(-aim.y, sim.y, bre.y * uu));
    nre.z = fmaf(are.z, sre.z, fmaf(-aim.z, sim.z, bre.z * uu));
    nre.w = fmaf(are.w, sre.w, fmaf(-aim.w, sim.w, bre.w * uu));
    nim.x = fmaf(are.x, sim.x, fmaf( aim.x, sre.x, bim.x * uu));
    nim.y = fmaf(are.y, sim.y, fmaf( aim.y, sre.y, bim.y * uu));
    nim.z = fmaf(are.z, sim.z, fmaf( aim.z, sre.z, bim.z * uu));
    nim.w = fmaf(are.w, sim.w, fmaf( aim.w, sre.w, bim.w * uu));

    __stcs((float4*)(ns_re + base), nre);
    __stcs((float4*)(ns_im + base), nim);

    float p = fmaf(cre.x, nre.x, -cim.x * nim.x)
            + fmaf(cre.y, nre.y, -cim.y * nim.y)
            + fmaf(cre.z, nre.z, -cim.z * nim.z)
            + fmaf(cre.w, nre.w, -cim.w * nim.w);
    p += __shfl_xor_sync(0xFFFFFFFFu, p, 4);
    p += __shfl_xor_sync(0xFFFFFFFFu, p, 2);
    p += __shfl_xor_sync(0xFFFFFFFFu, p, 1);

    if (q == 0) {
        float y = 2.0f * p + uu * D[h];
        float gel = 0.5f * y * (1.0f + erff(y * 0.7071067811865476f));
        __half hi = __float2half(gel);
        __half lo = __float2half(gel - __half2float(hi));
        g_Ahi[g] = hi;
        g_Alo[g] = lo;
    }
}

// ---------------------------------------------------------------------------
// Kernel 2: fp16 2-term GEMM via mma.sync.m16n8k16 + fused GLU epilogue.
// z = (Ahi + Alo) @ Wh^T ;  error limited to W's fp16 rounding (~1e-4 rel).
// CTA tile 128(M) x 64(N-perm), 8 warps, 2-stage cp.async, 2 CTAs/SM.
// ---------------------------------------------------------------------------
#define GT       256
#define TILE_M   128
#define TILE_N   64
#define KC       32
#define NKC      (HD / KC)            // 32
#define TILE_AB  (128 * KC * 2)       // 8192 bytes (A tiles, 128 rows)
#define TILE_BB  (64 * KC * 2)        // 4096 bytes (B tile, 64 rows)
#define STAGE_B  (2 * TILE_AB + TILE_BB)      // 20480
#define GEMM_SMEM (2 * STAGE_B)       // 40960
#define OFF_AHI  0
#define OFF_ALO  TILE_AB
#define OFF_B    (2 * TILE_AB)

__device__ __forceinline__ void load_stage(
    uint32_t st, int m0, int n0, int kc, int t)
{
    // Ahi: 512 segs, Alo: 512, B: 256 -> 1280 segs; 256 thr -> 5 each
    #pragma unroll
    for (int i = 0; i < 5; i++) {
        int idx = i * GT + t;
        const __half* gb;
        int row0, seg;
        uint32_t toff;
        if (idx < 512)        { gb = g_Ahi; row0 = m0; seg = idx;        toff = OFF_AHI; }
        else if (idx < 1024)  { gb = g_Alo; row0 = m0; seg = idx - 512;  toff = OFF_ALO; }
        else                  { gb = g_Bh;  row0 = n0; seg = idx - 1024; toff = OFF_B;   }
        int row  = seg >> 2;
        int slot = seg & 3;
        const char* g = (const char*)(gb + (size_t)(row0 + row) * HD + kc * KC)
                        + slot * 16;
        cp_async16(swz_addr(st + toff, row, slot), g);
    }
}

__global__ __launch_bounds__(GT, 2) void gemm_tc_kernel(
    const float* __restrict__ bias, float* __restrict__ out)
{
    extern __shared__ char smem[];
    uint32_t sb = smem_to_u32(smem);
    int t    = threadIdx.x;
    int wid  = t >> 5;
    int lane = t & 31;
    int wm   = wid & 1;              // M half (0/1)
    int wn   = wid >> 1;             // N quarter (0..3), 16 perm-cols each

    int n0 = blockIdx.x * TILE_N;    // permuted-W row range
    int m0 = blockIdx.y * TILE_M;

    float acc[4][2][4];
    #pragma unroll
    for (int mi = 0; mi < 4; mi++)
        #pragma unroll
        for (int ni = 0; ni < 2; ni++)
            #pragma unroll
            for (int r = 0; r < 4; r++)
                acc[mi][ni][r] = 0.0f;

    // Prologue
    load_stage(sb, m0, n0, 0, t);
    cp_async_commit();

    int lrow  = lane & 15;
    int lslot = lane >> 4;

    for (int kc = 0; kc < NKC; kc++) {
        uint32_t stage = sb + (kc & 1) * STAGE_B;

        if (kc + 1 < NKC) {
            load_stage(sb + ((kc + 1) & 1) * STAGE_B, m0, n0, kc + 1, t);
            cp_async_commit();
            cp_async_wait1();
        } else {
            cp_async_wait0();
        }
        __syncthreads();

        uint32_t stAhi = stage + OFF_AHI;
        uint32_t stAlo = stage + OFF_ALO;
        uint32_t stB   = stage + OFF_B;

        #pragma unroll
        for (int kk = 0; kk < 2; kk++) {
            uint32_t a_hi[4][4], a_lo[4][4], bfr[2][2];

            #pragma unroll
            for (int mi = 0; mi < 4; mi++) {
                int row = wm * 64 + mi * 16 + lrow;
                int slt = 2 * kk + lslot;
                LDMATRIX_X4(a_hi[mi][0], a_hi[mi][1], a_hi[mi][2], a_hi[mi][3],
                            swz_addr(stAhi, row, slt));
                LDMATRIX_X4(a_lo[mi][0], a_lo[mi][1], a_lo[mi][2], a_lo[mi][3],
                            swz_addr(stAlo, row, slt));
            }
            {
                int row = wn * 16 + lrow;
                int slt = 2 * kk + lslot;
                uint32_t q0, q1, q2, q3;
                LDMATRIX_X4(q0, q1, q2, q3, swz_addr(stB, row, slt));
                bfr[0][0] = q0; bfr[0][1] = q2;
                bfr[1][0] = q1; bfr[1][1] = q3;
            }

            // Term 1: Ahi * B
            #pragma unroll
            for (int mi = 0; mi < 4; mi++)
                #pragma unroll
                for (int ni = 0; ni < 2; ni++)
                    MMA_16816_F16(acc[mi][ni], a_hi[mi], bfr[ni][0], bfr[ni][1]);
            // Term 2: Alo * B
            #pragma unroll
            for (int mi = 0; mi < 4; mi++)
                #pragma unroll
                for (int ni = 0; ni < 2; ni++)
                    MMA_16816_F16(acc[mi][ni], a_lo[mi], bfr[ni][0], bfr[ni][1]);
        }
        __syncthreads();
    }

    // Fused GLU epilogue.
    int tr = lane >> 2;               // 0..7
    int tc = (lane & 3) * 2;
    int r_base = m0 + wm * 64;
    int c_base = n0 + wn * 16;
    #pragma unroll
    for (int mi = 0; mi < 4; mi++) {
        #pragma unroll
        for (int ni = 0; ni < 2; ni++) {
            int r = r_base + mi * 16 + tr;
            int j = (c_base + ni * 8 + tc) >> 1;
            float b0 = bias[j], b1 = bias[HD + j];
            float z1a = acc[mi][ni][0] + b0;
            float z2a = acc[mi][ni][1] + b1;
            float z1b = acc[mi][ni][2] + b0;
            float z2b = acc[mi][ni][3] + b1;
            out[(size_t)r * HD + j]       = z1a * (1.0f / (1.0f + __expf(-z2a)));
            out[(size_t)(r + 8) * HD + j] = z1b * (1.0f / (1.0f + __expf(-z2b)));
        }
    }
}

// ---------------------------------------------------------------------------
// launch
// ---------------------------------------------------------------------------
extern "C" void kernel_launch(void* const* d_in, const int* in_sizes, int n_in,
                              void* d_out, int out_size)
{
    const float* u     = (const float*)d_in[0];
    const float* st_re = (const float*)d_in[1];
    const float* st_im = (const float*)d_in[2];
    const float* dA_re = (const float*)d_in[3];
    const float* dA_im = (const float*)d_in[4];
    const float* dB_re = (const float*)d_in[5];
    const float* dB_im = (const float*)d_in[6];
    const float* C_re  = (const float*)d_in[7];
    const float* C_im  = (const float*)d_in[8];
    const float* D     = (const float*)d_in[9];
    const float* W     = (const float*)d_in[10];
    const float* bias  = (const float*)d_in[11];

    float* out   = (float*)d_out;
    float* y_out = out;                                    // [B, H]
    float* ns_re = out + (size_t)BSZ * HD;                 // [B, H, N]
    float* ns_im = out + (size_t)BSZ * HD + (size_t)BSZ * HD * NS;

    // 1) fused: convertW + s4 update
    fused_update_kernel<<<CONVW_BLOCKS + S4_BLOCKS, 256>>>(
        u, st_re, st_im, dA_re, dA_im, dB_re, dB_im, C_re, C_im, D, W,
        ns_re, ns_im);

    // 2) fp16 2-term tensor-core GEMM + fused GLU -> y_out
    static bool attr_set = false;
    if (!attr_set) {
        cudaFuncSetAttribute(gemm_tc_kernel,
                             cudaFuncAttributeMaxDynamicSharedMemorySize,
                             GEMM_SMEM);
        attr_set = true;
    }
    {
        dim3 grid(2 * HD / TILE_N, BSZ / TILE_M);   // (32, 8)
        gemm_tc_kernel<<<grid, GT, GEMM_SMEM>>>(bias, y_out);
    }

    (void)in_sizes; (void)n_in; (void)out_size;
}

// round 16
// speedup vs baseline: 1.2895x; 1.1819x over previous
#include <cuda_runtime.h>
#include <cuda_fp16.h>
#include <stdint.h>
#include <math.h>

// Problem constants (MetaS4: B=1024, H=1024, N=32)
#define BSZ 1024
#define HD  1024
#define NS  32

// ---------------------------------------------------------------------------
// Device scratch (allocation-free rule)
// g_Bh holds W in GLU-PERMUTED row order: row 2j = W[j], row 2j+1 = W[H+j]
// Single-term fp16 GEMM: z = fp16(y) @ fp16(Wperm)^T  (rel_err ~5e-4)
// ---------------------------------------------------------------------------
__device__ __align__(256) __half g_Ah[BSZ * HD];        // y fp16 [M,K]
__device__ __align__(256) __half g_Bh[2 * HD * HD];     // Wperm fp16 [2H,K]

// ---------------------------------------------------------------------------
// PTX helpers (baseline ISA only — no tcgen05 on this build's ptx target)
// ---------------------------------------------------------------------------
__device__ __forceinline__ uint32_t smem_to_u32(const void* p) {
    uint32_t a;
    asm("{ .reg .u64 t; cvta.to.shared.u64 t, %1; cvt.u32.u64 %0, t; }"
        : "=r"(a) : "l"(p));
    return a;
}
__device__ __forceinline__ void cp_async16(uint32_t smem_addr, const void* gptr) {
    asm volatile("cp.async.cg.shared.global [%0], [%1], 16;\n"
                 :: "r"(smem_addr), "l"(gptr) : "memory");
}
__device__ __forceinline__ void cp_async_commit() {
    asm volatile("cp.async.commit_group;\n" ::: "memory");
}
__device__ __forceinline__ void cp_async_wait1() {
    asm volatile("cp.async.wait_group 1;\n" ::: "memory");
}
__device__ __forceinline__ void cp_async_wait0() {
    asm volatile("cp.async.wait_group 0;\n" ::: "memory");
}

#define LDMATRIX_X4(r0, r1, r2, r3, addr) \
    asm volatile("ldmatrix.sync.aligned.m8n8.x4.shared.b16 {%0,%1,%2,%3}, [%4];" \
        : "=r"(r0), "=r"(r1), "=r"(r2), "=r"(r3) : "r"(addr))

#define MMA_16816_F16(acc, a, b0, b1) \
    asm volatile("mma.sync.aligned.m16n8k16.row.col.f32.f16.f16.f32 " \
        "{%0,%1,%2,%3}, {%4,%5,%6,%7}, {%8,%9}, {%0,%1,%2,%3};" \
        : "+f"((acc)[0]), "+f"((acc)[1]), "+f"((acc)[2]), "+f"((acc)[3]) \
        : "r"((a)[0]), "r"((a)[1]), "r"((a)[2]), "r"((a)[3]), \
          "r"(b0), "r"(b1))

// Swizzled smem address for a [rows][32 fp16] tile (64 B rows, 4x16B slots).
__device__ __forceinline__ uint32_t swz_addr(uint32_t tile_base, int row, int slot) {
    int s = (slot + ((row >> 1) & 3)) & 3;
    return tile_base + row * 64 + s * 16;
}

// ---------------------------------------------------------------------------
// Kernel 1 (FUSED): blocks [0, 2048)   -> convert W -> fp16 (permuted)
//                   blocks [2048, ...) -> s4 state update (R6 mapping)
// ---------------------------------------------------------------------------
#define CONVW_BLOCKS 2048
#define S4_BLOCKS    (BSZ * HD * 8 / 256)    // 32768

__global__ __launch_bounds__(256) void fused_update_kernel(
    const float* __restrict__ u,
    const float* __restrict__ st_re, const float* __restrict__ st_im,
    const float* __restrict__ dA_re, const float* __restrict__ dA_im,
    const float* __restrict__ dB_re, const float* __restrict__ dB_im,
    const float* __restrict__ C_re,  const float* __restrict__ C_im,
    const float* __restrict__ D,     const float* __restrict__ W,
    float* __restrict__ ns_re, float* __restrict__ ns_im)
{
    if (blockIdx.x < CONVW_BLOCKS) {
        // ---- convertW path: fp16, GLU-permuted rows ----
        int i  = blockIdx.x * 256 + threadIdx.x;
        int i4 = i * 4;
        int row = i4 >> 10;          // / HD
        int col = i4 & (HD - 1);
        int drow = (row < HD) ? (2 * row) : (2 * (row - HD) + 1);
        size_t dst = (size_t)drow * HD + col;

        float4 w = *(const float4*)(W + i4);
        __half h0 = __float2half(w.x);
        __half h1 = __float2half(w.y);
        __half h2 = __float2half(w.z);
        __half h3 = __float2half(w.w);
        uint32_t p0 = ((uint32_t)__half_as_ushort(h1) << 16) | __half_as_ushort(h0);
        uint32_t p1 = ((uint32_t)__half_as_ushort(h3) << 16) | __half_as_ushort(h2);
        *(uint2*)(g_Bh + dst) = make_uint2(p0, p1);
        return;
    }

    // ---- s4 path ----
    int t = (blockIdx.x - CONVW_BLOCKS) * 256 + threadIdx.x;
    int g = t >> 3;            // (b,h) flat id
    int q = t & 7;             // 4-n group index
    int h = g & (HD - 1);

    long base = (long)g * NS + q * 4;
    int  ph   = h * NS + q * 4;

    float4 sre = __ldcs((const float4*)(st_re + base));
    float4 sim = __ldcs((const float4*)(st_im + base));
    float4 are = *(const float4*)(dA_re + ph);
    float4 aim = *(const float4*)(dA_im + ph);
    float4 bre = *(const float4*)(dB_re + ph);
    float4 bim = *(const float4*)(dB_im + ph);
    float4 cre = *(const float4*)(C_re  + ph);
    float4 cim = *(const float4*)(C_im  + ph);
    float  uu  = u[g];

    float4 nre, nim;
    nre.x = fmaf(are.x, sre.x, fmaf(-aim.x, sim.x, bre.x * uu));
    nre.y = fmaf(are.y, sre.y, fmaf(-aim.y, sim.y, bre.y * uu));
    nre.z = fmaf(are.z, sre.z, fmaf(-aim.z, sim.z, bre.z * uu));
    nre.w = fmaf(are.w, sre.w, fmaf(-aim.w, sim.w, bre.w * uu));
    nim.x = fmaf(are.x, sim.x, fmaf( aim.x, sre.x, bim.x * uu));
    nim.y = fmaf(are.y, sim.y, fmaf( aim.y, sre.y, bim.y * uu));
    nim.z = fmaf(are.z, sim.z, fmaf( aim.z, sre.z, bim.z * uu));
    nim.w = fmaf(are.w, sim.w, fmaf( aim.w, sre.w, bim.w * uu));

    __stcs((float4*)(ns_re + base), nre);
    __stcs((float4*)(ns_im + base), nim);

    float p = fmaf(cre.x, nre.x, -cim.x * nim.x)
            + fmaf(cre.y, nre.y, -cim.y * nim.y)
            + fmaf(cre.z, nre.z, -cim.z * nim.z)
            + fmaf(cre.w, nre.w, -cim.w * nim.w);
    p += __shfl_xor_sync(0xFFFFFFFFu, p, 4);
    p += __shfl_xor_sync(0xFFFFFFFFu, p, 2);
    p += __shfl_xor_sync(0xFFFFFFFFu, p, 1);

    if (q == 0) {
        float y = 2.0f * p + uu * D[h];
        float gel = 0.5f * y * (1.0f + erff(y * 0.7071067811865476f));
        g_Ah[g] = __float2half(gel);
    }
}

// ---------------------------------------------------------------------------
// Kernel 2: single-term fp16 GEMM via mma.sync.m16n8k16 + fused GLU epilogue.
// CTA tile 128(M) x 64(N-perm), 8 warps, 2-stage cp.async, 3 CTAs/SM.
// ---------------------------------------------------------------------------
#define GT       256
#define TILE_M   128
#define TILE_N   64
#define KC       32
#define NKC      (HD / KC)            // 32
#define TILE_AB  (128 * KC * 2)       // 8192 bytes (A tile, 128 rows)
#define TILE_BB  (64 * KC * 2)        // 4096 bytes (B tile, 64 rows)
#define STAGE_B  (TILE_AB + TILE_BB)  // 12288
#define GEMM_SMEM (2 * STAGE_B)       // 24576
#define OFF_A    0
#define OFF_B    TILE_AB

__device__ __forceinline__ void load_stage(
    uint32_t st, int m0, int n0, int kc, int t)
{
    // A: 512 segs, B: 256 segs -> 768; 256 thr -> 3 each
    #pragma unroll
    for (int i = 0; i < 3; i++) {
        int idx = i * GT + t;
        const __half* gb;
        int row0, seg;
        uint32_t toff;
        if (idx < 512) { gb = g_Ah; row0 = m0; seg = idx;       toff = OFF_A; }
        else           { gb = g_Bh; row0 = n0; seg = idx - 512; toff = OFF_B; }
        int row  = seg >> 2;
        int slot = seg & 3;
        const char* g = (const char*)(gb + (size_t)(row0 + row) * HD + kc * KC)
                        + slot * 16;
        cp_async16(swz_addr(st + toff, row, slot), g);
    }
}

__global__ __launch_bounds__(GT, 3) void gemm_tc_kernel(
    const float* __restrict__ bias, float* __restrict__ out)
{
    extern __shared__ char smem[];
    uint32_t sb = smem_to_u32(smem);
    int t    = threadIdx.x;
    int wid  = t >> 5;
    int lane = t & 31;
    int wm   = wid & 1;              // M half (0/1)
    int wn   = wid >> 1;             // N quarter (0..3), 16 perm-cols each

    int n0 = blockIdx.x * TILE_N;    // permuted-W row range
    int m0 = blockIdx.y * TILE_M;

    float acc[4][2][4];
    #pragma unroll
    for (int mi = 0; mi < 4; mi++)
        #pragma unroll
        for (int ni = 0; ni < 2; ni++)
            #pragma unroll
            for (int r = 0; r < 4; r++)
                acc[mi][ni][r] = 0.0f;

    // Prologue
    load_stage(sb, m0, n0, 0, t);
    cp_async_commit();

    int lrow  = lane & 15;
    int lslot = lane >> 4;

    for (int kc = 0; kc < NKC; kc++) {
        uint32_t stage = sb + (kc & 1) * STAGE_B;

        if (kc + 1 < NKC) {
            load_stage(sb + ((kc + 1) & 1) * STAGE_B, m0, n0, kc + 1, t);
            cp_async_commit();
            cp_async_wait1();
        } else {
            cp_async_wait0();
        }
        __syncthreads();

        uint32_t stA = stage + OFF_A;
        uint32_t stB = stage + OFF_B;

        #pragma unroll
        for (int kk = 0; kk < 2; kk++) {
            uint32_t afr[4][4], bfr[2][2];

            #pragma unroll
            for (int mi = 0; mi < 4; mi++) {
                int row = wm * 64 + mi * 16 + lrow;
                int slt = 2 * kk + lslot;
                LDMATRIX_X4(afr[mi][0], afr[mi][1], afr[mi][2], afr[mi][3],
                            swz_addr(stA, row, slt));
            }
            {
                int row = wn * 16 + lrow;
                int slt = 2 * kk + lslot;
                uint32_t q0, q1, q2, q3;
                LDMATRIX_X4(q0, q1, q2, q3, swz_addr(stB, row, slt));
                bfr[0][0] = q0; bfr[0][1] = q2;
                bfr[1][0] = q1; bfr[1][1] = q3;
            }

            #pragma unroll
            for (int mi = 0; mi < 4; mi++)
                #pragma unroll
                for (int ni = 0; ni < 2; ni++)
                    MMA_16816_F16(acc[mi][ni], afr[mi], bfr[ni][0], bfr[ni][1]);
        }
        __syncthreads();
    }

    // Fused GLU epilogue.
    int tr = lane >> 2;               // 0..7
    int tc = (lane & 3) * 2;
    int r_base = m0 + wm * 64;
    int c_base = n0 + wn * 16;
    #pragma unroll
    for (int mi = 0; mi < 4; mi++) {
        #pragma unroll
        for (int ni = 0; ni < 2; ni++) {
            int r = r_base + mi * 16 + tr;
            int j = (c_base + ni * 8 + tc) >> 1;
            float b0 = bias[j], b1 = bias[HD + j];
            float z1a = acc[mi][ni][0] + b0;
            float z2a = acc[mi][ni][1] + b1;
            float z1b = acc[mi][ni][2] + b0;
            float z2b = acc[mi][ni][3] + b1;
            out[(size_t)r * HD + j]       = z1a * (1.0f / (1.0f + __expf(-z2a)));
            out[(size_t)(r + 8) * HD + j] = z1b * (1.0f / (1.0f + __expf(-z2b)));
        }
    }
}

// ---------------------------------------------------------------------------
// launch
// ---------------------------------------------------------------------------
extern "C" void kernel_launch(void* const* d_in, const int* in_sizes, int n_in,
                              void* d_out, int out_size)
{
    const float* u     = (const float*)d_in[0];
    const float* st_re = (const float*)d_in[1];
    const float* st_im = (const float*)d_in[2];
    const float* dA_re = (const float*)d_in[3];
    const float* dA_im = (const float*)d_in[4];
    const float* dB_re = (const float*)d_in[5];
    const float* dB_im = (const float*)d_in[6];
    const float* C_re  = (const float*)d_in[7];
    const float* C_im  = (const float*)d_in[8];
    const float* D     = (const float*)d_in[9];
    const float* W     = (const float*)d_in[10];
    const float* bias  = (const float*)d_in[11];

    float* out   = (float*)d_out;
    float* y_out = out;                                    // [B, H]
    float* ns_re = out + (size_t)BSZ * HD;                 // [B, H, N]
    float* ns_im = out + (size_t)BSZ * HD + (size_t)BSZ * HD * NS;

    // 1) fused: convertW + s4 update
    fused_update_kernel<<<CONVW_BLOCKS + S4_BLOCKS, 256>>>(
        u, st_re, st_im, dA_re, dA_im, dB_re, dB_im, C_re, C_im, D, W,
        ns_re, ns_im);

    // 2) single-term fp16 tensor-core GEMM + fused GLU -> y_out
    static bool attr_set = false;
    if (!attr_set) {
        cudaFuncSetAttribute(gemm_tc_kernel,
                             cudaFuncAttributeMaxDynamicSharedMemorySize,
                             GEMM_SMEM);
        attr_set = true;
    }
    {
        dim3 grid(2 * HD / TILE_N, BSZ / TILE_M);   // (32, 8)
        gemm_tc_kernel<<<grid, GT, GEMM_SMEM>>>(bias, y_out);
    }

    (void)in_sizes; (void)n_in; (void)out_size;
}